// round 8
// baseline (speedup 1.0000x reference)
#include <cuda_runtime.h>
#include <cuda_bf16.h>
#include <cuda_fp16.h>
#include <stdint.h>

#define NNODES 100000
#define NEDGES 1600000
#define FDIM   64
#define NCLS   2
#define STRIDE 64            // padded CSR row capacity (max deg ~45 for Poisson(16))

// Scratch (__device__ globals; no allocations allowed)
__device__ int   g_cursor[NNODES];
__device__ int   g_colp[NNODES * STRIDE];      // padded CSR columns
__device__ float g_dinv[NNODES];
__device__ __align__(16) __half2 g_hh[NNODES * 32];   // x @ W1, fp16 pairs
__device__ float g_h2[NNODES * NCLS];          // relu(agg1 + b1) @ W2

__device__ __forceinline__ int clampi(int v) {
    return min(max(v, 0), NNODES - 1);
}

// ---------------------------------------------------------------------------
// K1: zero cursor
__global__ void k_zero(void) {
    int i = blockIdx.x * blockDim.x + threadIdx.x;
    if (i < NNODES) g_cursor[i] = 0;
}

// K2: direct padded-CSR fill; 4 edges/thread via int4
__global__ void k_fill(const int* __restrict__ ei) {
    int i = blockIdx.x * blockDim.x + threadIdx.x;
    if (i >= NEDGES / 4) return;
    int4 rv = ((const int4*)ei)[i];
    int4 cv = ((const int4*)(ei + NEDGES))[i];
    #pragma unroll
    for (int j = 0; j < 4; j++) {
        int r = clampi(j == 0 ? rv.x : j == 1 ? rv.y : j == 2 ? rv.z : rv.w);
        int c = clampi(j == 0 ? cv.x : j == 1 ? cv.y : j == 2 ? cv.z : cv.w);
        int slot = atomicAdd(&g_cursor[r], 1);
        if (slot < STRIDE) g_colp[r * STRIDE + slot] = c;
    }
}

// K3: h = x @ W1 via packed f32x2 FMA; also computes dinv for this block's nodes.
// 256 thr, 32 nodes/block; writes fp16 half2 rows.
__global__ void __launch_bounds__(256) k_gemm1(const float* __restrict__ x,
                                               const float* __restrict__ W1) {
    __shared__ float4 xs[32][16];   // 32 node rows
    const int tid = threadIdx.x;
    const int g = tid >> 6;         // node sub-group 0..3
    const int t = tid & 63;         // output column
    const int base = blockIdx.x * 32;
    if (tid < 32)                   // dinv for this block's nodes (cursor is final)
        g_dinv[base + tid] = rsqrtf((float)g_cursor[base + tid] + 1.0f);
    unsigned long long Wc2[32];     // W1[:,t] packed by k-pairs
    #pragma unroll
    for (int k2 = 0; k2 < 32; k2++) {
        float w0 = W1[(2 * k2) * 64 + t];
        float w1 = W1[(2 * k2 + 1) * 64 + t];
        asm("mov.b64 %0,{%1,%2};" : "=l"(Wc2[k2]) : "f"(w0), "f"(w1));
    }
    const float4* x4 = (const float4*)(x + (size_t)base * FDIM);
    for (int i = tid; i < 32 * 16; i += 256) ((float4*)xs)[i] = x4[i];
    __syncthreads();
    #pragma unroll 1
    for (int jj = 0; jj < 8; jj++) {
        const int j = g * 8 + jj;
        unsigned long long accA = 0, accB = 0;
        #pragma unroll
        for (int k4 = 0; k4 < 16; k4++) {
            float4 xv = xs[j][k4];
            unsigned long long a01, a23;
            asm("mov.b64 %0,{%1,%2};" : "=l"(a01) : "f"(xv.x), "f"(xv.y));
            asm("mov.b64 %0,{%1,%2};" : "=l"(a23) : "f"(xv.z), "f"(xv.w));
            asm("fma.rn.f32x2 %0,%1,%2,%0;" : "+l"(accA) : "l"(a01), "l"(Wc2[2 * k4]));
            asm("fma.rn.f32x2 %0,%1,%2,%0;" : "+l"(accB) : "l"(a23), "l"(Wc2[2 * k4 + 1]));
        }
        float lo0, hi0, lo1, hi1;
        asm("mov.b64 {%0,%1},%2;" : "=f"(lo0), "=f"(hi0) : "l"(accA));
        asm("mov.b64 {%0,%1},%2;" : "=f"(lo1), "=f"(hi1) : "l"(accB));
        float acc = (lo0 + lo1) + (hi0 + hi1);
        float nb = __shfl_down_sync(~0u, acc, 1);   // col t+1 (same warp)
        if ((t & 1) == 0)
            g_hh[(size_t)(base + j) * 32 + (t >> 1)] = __floats2half2_rn(acc, nb);
    }
}

// K4: fused layer-1 gather + bias + ReLU + GEMM2 -> g_h2.
// Warp per node. Lanes cooperatively load (col, w) for 32 edges, shfl-broadcast,
// then coalesced half2 row gathers (4 in flight).
__global__ void __launch_bounds__(256) k_fused1(const float* __restrict__ b1,
                                                const float* __restrict__ W2) {
    const int warp = threadIdx.x >> 5;
    const int l = threadIdx.x & 31;
    const int n = blockIdx.x * 8 + warp;
    if (n >= NNODES) return;

    const float din = g_dinv[n];
    const int deg = min(g_cursor[n], STRIDE);
    const int base = n * STRIDE;

    float2 sv = __half22float2(g_hh[(size_t)n * 32 + l]);
    const float sl = din * din;
    float a0 = sl * sv.x, a1 = sl * sv.y;     // self loop

    for (int chunk = 0; chunk < deg; chunk += 32) {
        const int rem = deg - chunk;
        int c = 0; float w = 0.0f;
        if (l < rem) {
            c = g_colp[base + chunk + l];
            w = din * g_dinv[c];
        }
        const int m = min(rem, 32);
        int j = 0;
        for (; j + 4 <= m; j += 4) {
            int   c0 = __shfl_sync(~0u, c, j),     c1 = __shfl_sync(~0u, c, j + 1);
            int   c2 = __shfl_sync(~0u, c, j + 2), c3 = __shfl_sync(~0u, c, j + 3);
            float w0 = __shfl_sync(~0u, w, j),     w1 = __shfl_sync(~0u, w, j + 1);
            float w2 = __shfl_sync(~0u, w, j + 2), w3 = __shfl_sync(~0u, w, j + 3);
            __half2 h0 = g_hh[(size_t)c0 * 32 + l];
            __half2 h1 = g_hh[(size_t)c1 * 32 + l];
            __half2 h2 = g_hh[(size_t)c2 * 32 + l];
            __half2 h3 = g_hh[(size_t)c3 * 32 + l];
            float2 f;
            f = __half22float2(h0); a0 = fmaf(w0, f.x, a0); a1 = fmaf(w0, f.y, a1);
            f = __half22float2(h1); a0 = fmaf(w1, f.x, a0); a1 = fmaf(w1, f.y, a1);
            f = __half22float2(h2); a0 = fmaf(w2, f.x, a0); a1 = fmaf(w2, f.y, a1);
            f = __half22float2(h3); a0 = fmaf(w3, f.x, a0); a1 = fmaf(w3, f.y, a1);
        }
        for (; j < m; j++) {
            int   cj = __shfl_sync(~0u, c, j);
            float wj = __shfl_sync(~0u, w, j);
            float2 f = __half22float2(g_hh[(size_t)cj * 32 + l]);
            a0 = fmaf(wj, f.x, a0);
            a1 = fmaf(wj, f.y, a1);
        }
    }

    float v0 = fmaxf(a0 + b1[2 * l],     0.0f);
    float v1 = fmaxf(a1 + b1[2 * l + 1], 0.0f);

    // GEMM2: logits[n] = v @ W2 (64x2)
    float c0 = fmaf(v0, W2[(2 * l) * 2],     v1 * W2[(2 * l + 1) * 2]);
    float c1 = fmaf(v0, W2[(2 * l) * 2 + 1], v1 * W2[(2 * l + 1) * 2 + 1]);
    #pragma unroll
    for (int off = 16; off > 0; off >>= 1) {
        c0 += __shfl_down_sync(0xFFFFFFFFu, c0, off);
        c1 += __shfl_down_sync(0xFFFFFFFFu, c1, off);
    }
    if (l == 0) {
        g_h2[n * 2]     = c0;
        g_h2[n * 2 + 1] = c1;
    }
}

// K5: fused layer-2 gather + bias + softmax -> out.  Warp per node.
__global__ void k_fused2(const float* __restrict__ b2, float* __restrict__ out) {
    const int lane = threadIdx.x & 31;
    const int n = (blockIdx.x * blockDim.x + threadIdx.x) >> 5;
    if (n >= NNODES) return;
    const float din = g_dinv[n];
    const int deg = min(g_cursor[n], STRIDE);
    const int base = n * STRIDE;
    float a0 = 0.0f, a1 = 0.0f;
    for (int s = lane; s < deg; s += 32) {
        int c = g_colp[base + s];
        float w = din * g_dinv[c];
        a0 = fmaf(w, g_h2[c * 2],     a0);
        a1 = fmaf(w, g_h2[c * 2 + 1], a1);
    }
    #pragma unroll
    for (int off = 16; off > 0; off >>= 1) {
        a0 += __shfl_down_sync(0xFFFFFFFFu, a0, off);
        a1 += __shfl_down_sync(0xFFFFFFFFu, a1, off);
    }
    if (lane == 0) {
        float sl = din * din;
        float l0 = b2[0] + fmaf(sl, g_h2[n * 2],     a0);
        float l1 = b2[1] + fmaf(sl, g_h2[n * 2 + 1], a1);
        float m = fmaxf(l0, l1);
        float e0 = __expf(l0 - m), e1 = __expf(l1 - m);
        float inv = 1.0f / (e0 + e1);
        out[n * 2]     = e0 * inv;
        out[n * 2 + 1] = e1 * inv;
    }
}

extern "C" void kernel_launch(void* const* d_in, const int* in_sizes, int n_in,
                              void* d_out, int out_size) {
    const float* x  = (const float*)d_in[0];
    const int*   ei = (const int*)d_in[1];     // int32 (JAX x64 disabled)
    const float* W1 = (const float*)d_in[2];
    const float* b1 = (const float*)d_in[3];
    const float* W2 = (const float*)d_in[4];
    const float* b2 = (const float*)d_in[5];
    float* out = (float*)d_out;

    const int T = 256;
    k_zero   <<<(NNODES + T - 1) / T, T>>>();
    k_fill   <<<(NEDGES / 4 + T - 1) / T, T>>>(ei);
    k_gemm1  <<<NNODES / 32, 256>>>(x, W1);
    k_fused1 <<<(NNODES + 7) / 8, 256>>>(b1, W2);
    k_fused2 <<<(NNODES * 32 + T - 1) / T, T>>>(b2, out);
}

// round 9
// speedup vs baseline: 1.3569x; 1.3569x over previous
#include <cuda_runtime.h>
#include <cuda_bf16.h>
#include <cuda_fp16.h>
#include <stdint.h>

#define NNODES 100000
#define NEDGES 1600000
#define FDIM   64
#define NCLS   2
#define STRIDE 64            // padded CSR row capacity (max deg ~45 for Poisson(16))

// Scratch (__device__ globals; no allocations allowed)
__device__ int   g_cursor[NNODES];
__device__ int   g_colp[NNODES * STRIDE];      // padded CSR columns
__device__ __align__(8) int2 g_cwp[NNODES * STRIDE];  // padded {col, bits(dinv[col])}
__device__ float g_dinv[NNODES];
__device__ __align__(16) __half2 g_hh[NNODES * 32];   // x @ W1, fp16 pairs
__device__ float g_h2[NNODES * NCLS];          // relu(agg1 + b1) @ W2

__device__ __forceinline__ int clampi(int v) {
    return min(max(v, 0), NNODES - 1);
}

// ---------------------------------------------------------------------------
// K1: zero cursor
__global__ void k_zero(void) {
    int i = blockIdx.x * blockDim.x + threadIdx.x;
    if (i < NNODES) g_cursor[i] = 0;
}

// K2: direct padded-CSR fill (cols only); 4 edges/thread via int4
__global__ void k_fill(const int* __restrict__ ei) {
    int i = blockIdx.x * blockDim.x + threadIdx.x;
    if (i >= NEDGES / 4) return;
    int4 rv = ((const int4*)ei)[i];
    int4 cv = ((const int4*)(ei + NEDGES))[i];
    #pragma unroll
    for (int j = 0; j < 4; j++) {
        int r = clampi(j == 0 ? rv.x : j == 1 ? rv.y : j == 2 ? rv.z : rv.w);
        int c = clampi(j == 0 ? cv.x : j == 1 ? cv.y : j == 2 ? cv.z : cv.w);
        int slot = atomicAdd(&g_cursor[r], 1);
        if (slot < STRIDE) g_colp[r * STRIDE + slot] = c;
    }
}

// K3: dinv from final degree
__global__ void k_dinv(void) {
    int i = blockIdx.x * blockDim.x + threadIdx.x;
    if (i < NNODES) g_dinv[i] = rsqrtf((float)g_cursor[i] + 1.0f);
}

// K4: expand cols -> (col, dinv[col]) pairs. Warp per node, lanes over slots.
__global__ void __launch_bounds__(256) k_weights(void) {
    const int warp = threadIdx.x >> 5;
    const int l = threadIdx.x & 31;
    const int n = blockIdx.x * 8 + warp;
    if (n >= NNODES) return;
    const int deg = min(g_cursor[n], STRIDE);
    const int base = n * STRIDE;
    for (int s = l; s < deg; s += 32) {
        int c = g_colp[base + s];
        g_cwp[base + s] = make_int2(c, __float_as_int(g_dinv[c]));
    }
}

// K5: h = x @ W1 via packed f32x2 FMA; 256 thr, 32 nodes/block; fp16 output.
__global__ void __launch_bounds__(256) k_gemm1(const float* __restrict__ x,
                                               const float* __restrict__ W1) {
    __shared__ float4 xs[32][16];   // 32 node rows
    const int tid = threadIdx.x;
    const int g = tid >> 6;         // node sub-group 0..3
    const int t = tid & 63;         // output column
    const int base = blockIdx.x * 32;
    unsigned long long Wc2[32];     // W1[:,t] packed by k-pairs
    #pragma unroll
    for (int k2 = 0; k2 < 32; k2++) {
        float w0 = W1[(2 * k2) * 64 + t];
        float w1 = W1[(2 * k2 + 1) * 64 + t];
        asm("mov.b64 %0,{%1,%2};" : "=l"(Wc2[k2]) : "f"(w0), "f"(w1));
    }
    const float4* x4 = (const float4*)(x + (size_t)base * FDIM);
    for (int i = tid; i < 32 * 16; i += 256) ((float4*)xs)[i] = x4[i];
    __syncthreads();
    #pragma unroll 1
    for (int jj = 0; jj < 8; jj++) {
        const int j = g * 8 + jj;
        unsigned long long accA = 0, accB = 0;
        #pragma unroll
        for (int k4 = 0; k4 < 16; k4++) {
            float4 xv = xs[j][k4];
            unsigned long long a01, a23;
            asm("mov.b64 %0,{%1,%2};" : "=l"(a01) : "f"(xv.x), "f"(xv.y));
            asm("mov.b64 %0,{%1,%2};" : "=l"(a23) : "f"(xv.z), "f"(xv.w));
            asm("fma.rn.f32x2 %0,%1,%2,%0;" : "+l"(accA) : "l"(a01), "l"(Wc2[2 * k4]));
            asm("fma.rn.f32x2 %0,%1,%2,%0;" : "+l"(accB) : "l"(a23), "l"(Wc2[2 * k4 + 1]));
        }
        float lo0, hi0, lo1, hi1;
        asm("mov.b64 {%0,%1},%2;" : "=f"(lo0), "=f"(hi0) : "l"(accA));
        asm("mov.b64 {%0,%1},%2;" : "=f"(lo1), "=f"(hi1) : "l"(accB));
        float acc = (lo0 + lo1) + (hi0 + hi1);
        float nb = __shfl_down_sync(~0u, acc, 1);   // col t+1 (same warp)
        if ((t & 1) == 0)
            g_hh[(size_t)(base + j) * 32 + (t >> 1)] = __floats2half2_rn(acc, nb);
    }
}

// K6: fused layer-1 gather + bias + ReLU + GEMM2 -> g_h2.
// Warp per node; uniform int2 loads + unroll-8 half2 row gathers (R7 pattern).
__global__ void __launch_bounds__(256) k_fused1(const float* __restrict__ b1,
                                                const float* __restrict__ W2) {
    const int warp = threadIdx.x >> 5;
    const int l = threadIdx.x & 31;
    const int n = blockIdx.x * 8 + warp;
    if (n >= NNODES) return;

    const float din = g_dinv[n];
    const int deg = min(g_cursor[n], STRIDE);
    const int base = n * STRIDE;

    float2 sv = __half22float2(g_hh[(size_t)n * 32 + l]);
    const float sl = din * din;
    float a0 = sl * sv.x, a1 = sl * sv.y;     // self loop

    int s = 0;
    for (; s + 8 <= deg; s += 8) {
        int2 cw0 = g_cwp[base + s],     cw1 = g_cwp[base + s + 1];
        int2 cw2 = g_cwp[base + s + 2], cw3 = g_cwp[base + s + 3];
        int2 cw4 = g_cwp[base + s + 4], cw5 = g_cwp[base + s + 5];
        int2 cw6 = g_cwp[base + s + 6], cw7 = g_cwp[base + s + 7];
        __half2 h0 = g_hh[(size_t)cw0.x * 32 + l];
        __half2 h1 = g_hh[(size_t)cw1.x * 32 + l];
        __half2 h2 = g_hh[(size_t)cw2.x * 32 + l];
        __half2 h3 = g_hh[(size_t)cw3.x * 32 + l];
        __half2 h4 = g_hh[(size_t)cw4.x * 32 + l];
        __half2 h5 = g_hh[(size_t)cw5.x * 32 + l];
        __half2 h6 = g_hh[(size_t)cw6.x * 32 + l];
        __half2 h7 = g_hh[(size_t)cw7.x * 32 + l];
        float w0 = din * __int_as_float(cw0.y);
        float w1 = din * __int_as_float(cw1.y);
        float w2 = din * __int_as_float(cw2.y);
        float w3 = din * __int_as_float(cw3.y);
        float w4 = din * __int_as_float(cw4.y);
        float w5 = din * __int_as_float(cw5.y);
        float w6 = din * __int_as_float(cw6.y);
        float w7 = din * __int_as_float(cw7.y);
        float2 f;
        f = __half22float2(h0); a0 = fmaf(w0, f.x, a0); a1 = fmaf(w0, f.y, a1);
        f = __half22float2(h1); a0 = fmaf(w1, f.x, a0); a1 = fmaf(w1, f.y, a1);
        f = __half22float2(h2); a0 = fmaf(w2, f.x, a0); a1 = fmaf(w2, f.y, a1);
        f = __half22float2(h3); a0 = fmaf(w3, f.x, a0); a1 = fmaf(w3, f.y, a1);
        f = __half22float2(h4); a0 = fmaf(w4, f.x, a0); a1 = fmaf(w4, f.y, a1);
        f = __half22float2(h5); a0 = fmaf(w5, f.x, a0); a1 = fmaf(w5, f.y, a1);
        f = __half22float2(h6); a0 = fmaf(w6, f.x, a0); a1 = fmaf(w6, f.y, a1);
        f = __half22float2(h7); a0 = fmaf(w7, f.x, a0); a1 = fmaf(w7, f.y, a1);
    }
    for (; s < deg; s++) {
        int2 cw = g_cwp[base + s];
        float w = din * __int_as_float(cw.y);
        float2 f = __half22float2(g_hh[(size_t)cw.x * 32 + l]);
        a0 = fmaf(w, f.x, a0);
        a1 = fmaf(w, f.y, a1);
    }

    float v0 = fmaxf(a0 + b1[2 * l],     0.0f);
    float v1 = fmaxf(a1 + b1[2 * l + 1], 0.0f);

    // GEMM2: logits[n] = v @ W2 (64x2)
    float c0 = fmaf(v0, W2[(2 * l) * 2],     v1 * W2[(2 * l + 1) * 2]);
    float c1 = fmaf(v0, W2[(2 * l) * 2 + 1], v1 * W2[(2 * l + 1) * 2 + 1]);
    #pragma unroll
    for (int off = 16; off > 0; off >>= 1) {
        c0 += __shfl_down_sync(0xFFFFFFFFu, c0, off);
        c1 += __shfl_down_sync(0xFFFFFFFFu, c1, off);
    }
    if (l == 0) {
        g_h2[n * 2]     = c0;
        g_h2[n * 2 + 1] = c1;
    }
}

// K7: fused layer-2 gather + bias + softmax -> out.  Warp per node.
__global__ void k_fused2(const float* __restrict__ b2, float* __restrict__ out) {
    const int lane = threadIdx.x & 31;
    const int n = (blockIdx.x * blockDim.x + threadIdx.x) >> 5;
    if (n >= NNODES) return;
    const float din = g_dinv[n];
    const int deg = min(g_cursor[n], STRIDE);
    const int base = n * STRIDE;
    float a0 = 0.0f, a1 = 0.0f;
    for (int s = lane; s < deg; s += 32) {
        int2 cw = g_cwp[base + s];
        float w = din * __int_as_float(cw.y);
        a0 = fmaf(w, g_h2[cw.x * 2],     a0);
        a1 = fmaf(w, g_h2[cw.x * 2 + 1], a1);
    }
    #pragma unroll
    for (int off = 16; off > 0; off >>= 1) {
        a0 += __shfl_down_sync(0xFFFFFFFFu, a0, off);
        a1 += __shfl_down_sync(0xFFFFFFFFu, a1, off);
    }
    if (lane == 0) {
        float sl = din * din;
        float l0 = b2[0] + fmaf(sl, g_h2[n * 2],     a0);
        float l1 = b2[1] + fmaf(sl, g_h2[n * 2 + 1], a1);
        float m = fmaxf(l0, l1);
        float e0 = __expf(l0 - m), e1 = __expf(l1 - m);
        float inv = 1.0f / (e0 + e1);
        out[n * 2]     = e0 * inv;
        out[n * 2 + 1] = e1 * inv;
    }
}

extern "C" void kernel_launch(void* const* d_in, const int* in_sizes, int n_in,
                              void* d_out, int out_size) {
    const float* x  = (const float*)d_in[0];
    const int*   ei = (const int*)d_in[1];     // int32 (JAX x64 disabled)
    const float* W1 = (const float*)d_in[2];
    const float* b1 = (const float*)d_in[3];
    const float* W2 = (const float*)d_in[4];
    const float* b2 = (const float*)d_in[5];
    float* out = (float*)d_out;

    const int T = 256;
    k_zero    <<<(NNODES + T - 1) / T, T>>>();
    k_fill    <<<(NEDGES / 4 + T - 1) / T, T>>>(ei);
    k_dinv    <<<(NNODES + T - 1) / T, T>>>();
    k_weights <<<(NNODES + 7) / 8, 256>>>();
    k_gemm1   <<<NNODES / 32, 256>>>(x, W1);
    k_fused1  <<<(NNODES + 7) / 8, 256>>>(b1, W2);
    k_fused2  <<<(NNODES * 32 + T - 1) / T, T>>>(b2, out);
}

// round 10
// speedup vs baseline: 1.4837x; 1.0935x over previous
#include <cuda_runtime.h>
#include <cuda_bf16.h>
#include <cuda_fp16.h>
#include <stdint.h>

#define NNODES 100000
#define NEDGES 1600000
#define FDIM   64
#define NCLS   2
#define STRIDE 64            // padded CSR row capacity (max deg ~45 for Poisson(16))

// Scratch (__device__ globals; no allocations allowed)
__device__ int   g_cursor[NNODES];
__device__ __align__(16) int g_colp[NNODES * STRIDE];  // padded CSR columns
__device__ float g_dinv[NNODES];
__device__ __align__(16) __half2 g_hh[NNODES * 32];    // x @ W1, fp16 pairs
__device__ float g_h2[NNODES * NCLS];                  // relu(agg1 + b1) @ W2

__device__ __forceinline__ int clampi(int v) {
    return min(max(v, 0), NNODES - 1);
}

// ---------------------------------------------------------------------------
// K1: zero cursor
__global__ void k_zero(void) {
    int i = blockIdx.x * blockDim.x + threadIdx.x;
    if (i < NNODES) g_cursor[i] = 0;
}

// K2: direct padded-CSR fill (cols only); 4 edges/thread via int4
__global__ void k_fill(const int* __restrict__ ei) {
    int i = blockIdx.x * blockDim.x + threadIdx.x;
    if (i >= NEDGES / 4) return;
    int4 rv = ((const int4*)ei)[i];
    int4 cv = ((const int4*)(ei + NEDGES))[i];
    #pragma unroll
    for (int j = 0; j < 4; j++) {
        int r = clampi(j == 0 ? rv.x : j == 1 ? rv.y : j == 2 ? rv.z : rv.w);
        int c = clampi(j == 0 ? cv.x : j == 1 ? cv.y : j == 2 ? cv.z : cv.w);
        int slot = atomicAdd(&g_cursor[r], 1);
        if (slot < STRIDE) g_colp[r * STRIDE + slot] = c;
    }
}

// K3: dinv from final degree
__global__ void k_dinv(void) {
    int i = blockIdx.x * blockDim.x + threadIdx.x;
    if (i < NNODES) g_dinv[i] = rsqrtf((float)g_cursor[i] + 1.0f);
}

// K4: h = x @ W1 via packed f32x2 FMA; 256 thr, 32 nodes/block; fp16 output.
__global__ void __launch_bounds__(256) k_gemm1(const float* __restrict__ x,
                                               const float* __restrict__ W1) {
    __shared__ float4 xs[32][16];   // 32 node rows
    const int tid = threadIdx.x;
    const int g = tid >> 6;         // node sub-group 0..3
    const int t = tid & 63;         // output column
    const int base = blockIdx.x * 32;
    unsigned long long Wc2[32];     // W1[:,t] packed by k-pairs
    #pragma unroll
    for (int k2 = 0; k2 < 32; k2++) {
        float w0 = W1[(2 * k2) * 64 + t];
        float w1 = W1[(2 * k2 + 1) * 64 + t];
        asm("mov.b64 %0,{%1,%2};" : "=l"(Wc2[k2]) : "f"(w0), "f"(w1));
    }
    const float4* x4 = (const float4*)(x + (size_t)base * FDIM);
    for (int i = tid; i < 32 * 16; i += 256) ((float4*)xs)[i] = x4[i];
    __syncthreads();
    #pragma unroll 1
    for (int jj = 0; jj < 8; jj++) {
        const int j = g * 8 + jj;
        unsigned long long accA = 0, accB = 0;
        #pragma unroll
        for (int k4 = 0; k4 < 16; k4++) {
            float4 xv = xs[j][k4];
            unsigned long long a01, a23;
            asm("mov.b64 %0,{%1,%2};" : "=l"(a01) : "f"(xv.x), "f"(xv.y));
            asm("mov.b64 %0,{%1,%2};" : "=l"(a23) : "f"(xv.z), "f"(xv.w));
            asm("fma.rn.f32x2 %0,%1,%2,%0;" : "+l"(accA) : "l"(a01), "l"(Wc2[2 * k4]));
            asm("fma.rn.f32x2 %0,%1,%2,%0;" : "+l"(accB) : "l"(a23), "l"(Wc2[2 * k4 + 1]));
        }
        float lo0, hi0, lo1, hi1;
        asm("mov.b64 {%0,%1},%2;" : "=f"(lo0), "=f"(hi0) : "l"(accA));
        asm("mov.b64 {%0,%1},%2;" : "=f"(lo1), "=f"(hi1) : "l"(accB));
        float acc = (lo0 + lo1) + (hi0 + hi1);
        float nb = __shfl_down_sync(~0u, acc, 1);   // col t+1 (same warp)
        if ((t & 1) == 0)
            g_hh[(size_t)(base + j) * 32 + (t >> 1)] = __floats2half2_rn(acc, nb);
    }
}

// K5: fused layer-1 gather + bias + ReLU + GEMM2 -> g_h2.
// Warp per node. Per 8 edges: 2 uniform int4 col loads, 8 uniform dinv
// gathers, 8 independent coalesced half2 row gathers.
__global__ void __launch_bounds__(256) k_fused1(const float* __restrict__ b1,
                                                const float* __restrict__ W2) {
    const int warp = threadIdx.x >> 5;
    const int l = threadIdx.x & 31;
    const int n = blockIdx.x * 8 + warp;
    if (n >= NNODES) return;

    const float din = g_dinv[n];
    const int deg = min(g_cursor[n], STRIDE);
    const int base = n * STRIDE;

    float2 sv = __half22float2(g_hh[(size_t)n * 32 + l]);
    const float sl = din * din;
    float a0 = sl * sv.x, a1 = sl * sv.y;     // self loop

    int s = 0;
    for (; s + 8 <= deg; s += 8) {
        int4 cA = *(const int4*)&g_colp[base + s];      // uniform 16B broadcast
        int4 cB = *(const int4*)&g_colp[base + s + 4];
        float d0 = g_dinv[cA.x], d1 = g_dinv[cA.y];
        float d2 = g_dinv[cA.z], d3 = g_dinv[cA.w];
        float d4 = g_dinv[cB.x], d5 = g_dinv[cB.y];
        float d6 = g_dinv[cB.z], d7 = g_dinv[cB.w];
        __half2 h0 = g_hh[(size_t)cA.x * 32 + l];
        __half2 h1 = g_hh[(size_t)cA.y * 32 + l];
        __half2 h2 = g_hh[(size_t)cA.z * 32 + l];
        __half2 h3 = g_hh[(size_t)cA.w * 32 + l];
        __half2 h4 = g_hh[(size_t)cB.x * 32 + l];
        __half2 h5 = g_hh[(size_t)cB.y * 32 + l];
        __half2 h6 = g_hh[(size_t)cB.z * 32 + l];
        __half2 h7 = g_hh[(size_t)cB.w * 32 + l];
        float w0 = din * d0, w1 = din * d1, w2 = din * d2, w3 = din * d3;
        float w4 = din * d4, w5 = din * d5, w6 = din * d6, w7 = din * d7;
        float2 f;
        f = __half22float2(h0); a0 = fmaf(w0, f.x, a0); a1 = fmaf(w0, f.y, a1);
        f = __half22float2(h1); a0 = fmaf(w1, f.x, a0); a1 = fmaf(w1, f.y, a1);
        f = __half22float2(h2); a0 = fmaf(w2, f.x, a0); a1 = fmaf(w2, f.y, a1);
        f = __half22float2(h3); a0 = fmaf(w3, f.x, a0); a1 = fmaf(w3, f.y, a1);
        f = __half22float2(h4); a0 = fmaf(w4, f.x, a0); a1 = fmaf(w4, f.y, a1);
        f = __half22float2(h5); a0 = fmaf(w5, f.x, a0); a1 = fmaf(w5, f.y, a1);
        f = __half22float2(h6); a0 = fmaf(w6, f.x, a0); a1 = fmaf(w6, f.y, a1);
        f = __half22float2(h7); a0 = fmaf(w7, f.x, a0); a1 = fmaf(w7, f.y, a1);
    }
    for (; s < deg; s++) {
        int c = g_colp[base + s];
        float w = din * g_dinv[c];
        float2 f = __half22float2(g_hh[(size_t)c * 32 + l]);
        a0 = fmaf(w, f.x, a0);
        a1 = fmaf(w, f.y, a1);
    }

    float v0 = fmaxf(a0 + b1[2 * l],     0.0f);
    float v1 = fmaxf(a1 + b1[2 * l + 1], 0.0f);

    // GEMM2: logits[n] = v @ W2 (64x2)
    float c0 = fmaf(v0, W2[(2 * l) * 2],     v1 * W2[(2 * l + 1) * 2]);
    float c1 = fmaf(v0, W2[(2 * l) * 2 + 1], v1 * W2[(2 * l + 1) * 2 + 1]);
    #pragma unroll
    for (int off = 16; off > 0; off >>= 1) {
        c0 += __shfl_down_sync(0xFFFFFFFFu, c0, off);
        c1 += __shfl_down_sync(0xFFFFFFFFu, c1, off);
    }
    if (l == 0) {
        g_h2[n * 2]     = c0;
        g_h2[n * 2 + 1] = c1;
    }
}

// K6: fused layer-2 gather + bias + softmax -> out.  Warp per node.
__global__ void k_fused2(const float* __restrict__ b2, float* __restrict__ out) {
    const int lane = threadIdx.x & 31;
    const int n = (blockIdx.x * blockDim.x + threadIdx.x) >> 5;
    if (n >= NNODES) return;
    const float din = g_dinv[n];
    const int deg = min(g_cursor[n], STRIDE);
    const int base = n * STRIDE;
    float a0 = 0.0f, a1 = 0.0f;
    for (int s = lane; s < deg; s += 32) {
        int c = g_colp[base + s];
        float w = din * g_dinv[c];
        a0 = fmaf(w, g_h2[c * 2],     a0);
        a1 = fmaf(w, g_h2[c * 2 + 1], a1);
    }
    #pragma unroll
    for (int off = 16; off > 0; off >>= 1) {
        a0 += __shfl_down_sync(0xFFFFFFFFu, a0, off);
        a1 += __shfl_down_sync(0xFFFFFFFFu, a1, off);
    }
    if (lane == 0) {
        float sl = din * din;
        float l0 = b2[0] + fmaf(sl, g_h2[n * 2],     a0);
        float l1 = b2[1] + fmaf(sl, g_h2[n * 2 + 1], a1);
        float m = fmaxf(l0, l1);
        float e0 = __expf(l0 - m), e1 = __expf(l1 - m);
        float inv = 1.0f / (e0 + e1);
        out[n * 2]     = e0 * inv;
        out[n * 2 + 1] = e1 * inv;
    }
}

extern "C" void kernel_launch(void* const* d_in, const int* in_sizes, int n_in,
                              void* d_out, int out_size) {
    const float* x  = (const float*)d_in[0];
    const int*   ei = (const int*)d_in[1];     // int32 (JAX x64 disabled)
    const float* W1 = (const float*)d_in[2];
    const float* b1 = (const float*)d_in[3];
    const float* W2 = (const float*)d_in[4];
    const float* b2 = (const float*)d_in[5];
    float* out = (float*)d_out;

    const int T = 256;
    k_zero   <<<(NNODES + T - 1) / T, T>>>();
    k_fill   <<<(NEDGES / 4 + T - 1) / T, T>>>(ei);
    k_dinv   <<<(NNODES + T - 1) / T, T>>>();
    k_gemm1  <<<NNODES / 32, 256>>>(x, W1);
    k_fused1 <<<(NNODES + 7) / 8, 256>>>(b1, W2);
    k_fused2 <<<(NNODES * 32 + T - 1) / T, T>>>(b2, out);
}

// round 11
// speedup vs baseline: 1.5908x; 1.0722x over previous
#include <cuda_runtime.h>
#include <cuda_bf16.h>
#include <cuda_fp16.h>
#include <stdint.h>

#define NNODES 100000
#define NEDGES 1600000
#define FDIM   64
#define NCLS   2
#define STRIDE 64            // padded CSR row capacity (max deg ~45 for Poisson(16))

// Scratch (__device__ globals; no allocations allowed)
__device__ int   g_cursor[NNODES];
__device__ __align__(16) int g_colp[NNODES * STRIDE];  // padded CSR columns
__device__ float g_dinv[NNODES];
__device__ __align__(16) __half2 g_hh[NNODES * 32];    // x @ W1, fp16 pairs
__device__ float g_h2[NNODES * NCLS];                  // relu(agg1 + b1) @ W2

__device__ __forceinline__ int clampi(int v) {
    return min(max(v, 0), NNODES - 1);
}

// ---------------------------------------------------------------------------
// K1: zero cursor
__global__ void k_zero(void) {
    int i = blockIdx.x * blockDim.x + threadIdx.x;
    if (i < NNODES) g_cursor[i] = 0;
}

// K2: direct padded-CSR fill (cols only); 4 edges/thread via int4
__global__ void k_fill(const int* __restrict__ ei) {
    int i = blockIdx.x * blockDim.x + threadIdx.x;
    if (i >= NEDGES / 4) return;
    int4 rv = ((const int4*)ei)[i];
    int4 cv = ((const int4*)(ei + NEDGES))[i];
    #pragma unroll
    for (int j = 0; j < 4; j++) {
        int r = clampi(j == 0 ? rv.x : j == 1 ? rv.y : j == 2 ? rv.z : rv.w);
        int c = clampi(j == 0 ? cv.x : j == 1 ? cv.y : j == 2 ? cv.z : cv.w);
        int slot = atomicAdd(&g_cursor[r], 1);
        if (slot < STRIDE) g_colp[r * STRIDE + slot] = c;
    }
}

// K3: dinv from final degree
__global__ void k_dinv(void) {
    int i = blockIdx.x * blockDim.x + threadIdx.x;
    if (i < NNODES) g_dinv[i] = rsqrtf((float)g_cursor[i] + 1.0f);
}

// K4: h = x @ W1, 2D register-blocked. Block = 256 thr, tile 64 nodes x 64 cols,
// thread computes 4x4; ~40 regs -> high occupancy. fp16 half2 output.
__global__ void __launch_bounds__(256) k_gemm1(const float* __restrict__ x,
                                               const float* __restrict__ W1) {
    __shared__ float xs[64][65];    // [node][k], padded: column reads conflict-free
    __shared__ float Ws[64][64];    // [k][col]
    const int tid = threadIdx.x;
    const int base = blockIdx.x * 64;

    // Load W1 (4096 floats = 1024 float4)
    {
        const float4* w4 = (const float4*)W1;
        float4* ws4 = (float4*)Ws;
        #pragma unroll
        for (int i = 0; i < 4; i++) ws4[tid + i * 256] = w4[tid + i * 256];
    }
    // Load x tile: 4 threads per row, each covers 16 cols (4 float4)
    {
        const int row = tid >> 2;       // 0..63
        const int seg = tid & 3;        // 0..3
        const bool ok = (base + row) < NNODES;
        const float4* x4 = (const float4*)(x + (size_t)(base + row) * FDIM);
        #pragma unroll
        for (int i = 0; i < 4; i++) {
            float4 v = ok ? x4[seg * 4 + i] : make_float4(0.f, 0.f, 0.f, 0.f);
            const int k0 = (seg * 4 + i) * 4;
            xs[row][k0]     = v.x;
            xs[row][k0 + 1] = v.y;
            xs[row][k0 + 2] = v.z;
            xs[row][k0 + 3] = v.w;
        }
    }
    __syncthreads();

    const int ng = tid >> 4;   // node group 0..15 (4 nodes)
    const int cg = tid & 15;   // col group 0..15 (4 cols)
    float acc[4][4];
    #pragma unroll
    for (int i = 0; i < 4; i++)
        #pragma unroll
        for (int j = 0; j < 4; j++) acc[i][j] = 0.0f;

    #pragma unroll 4
    for (int k = 0; k < 64; k++) {
        float4 wv = *(const float4*)&Ws[k][cg * 4];
        float xa0 = xs[ng * 4 + 0][k];
        float xa1 = xs[ng * 4 + 1][k];
        float xa2 = xs[ng * 4 + 2][k];
        float xa3 = xs[ng * 4 + 3][k];
        acc[0][0] = fmaf(xa0, wv.x, acc[0][0]);
        acc[0][1] = fmaf(xa0, wv.y, acc[0][1]);
        acc[0][2] = fmaf(xa0, wv.z, acc[0][2]);
        acc[0][3] = fmaf(xa0, wv.w, acc[0][3]);
        acc[1][0] = fmaf(xa1, wv.x, acc[1][0]);
        acc[1][1] = fmaf(xa1, wv.y, acc[1][1]);
        acc[1][2] = fmaf(xa1, wv.z, acc[1][2]);
        acc[1][3] = fmaf(xa1, wv.w, acc[1][3]);
        acc[2][0] = fmaf(xa2, wv.x, acc[2][0]);
        acc[2][1] = fmaf(xa2, wv.y, acc[2][1]);
        acc[2][2] = fmaf(xa2, wv.z, acc[2][2]);
        acc[2][3] = fmaf(xa2, wv.w, acc[2][3]);
        acc[3][0] = fmaf(xa3, wv.x, acc[3][0]);
        acc[3][1] = fmaf(xa3, wv.y, acc[3][1]);
        acc[3][2] = fmaf(xa3, wv.z, acc[3][2]);
        acc[3][3] = fmaf(xa3, wv.w, acc[3][3]);
    }

    #pragma unroll
    for (int i = 0; i < 4; i++) {
        const int node = base + ng * 4 + i;
        if (node < NNODES) {
            __half2 p0 = __floats2half2_rn(acc[i][0], acc[i][1]);
            __half2 p1 = __floats2half2_rn(acc[i][2], acc[i][3]);
            uint2 pk;
            pk.x = *(unsigned*)&p0;
            pk.y = *(unsigned*)&p1;
            *(uint2*)&g_hh[(size_t)node * 32 + cg * 2] = pk;
        }
    }
}

// K5: fused layer-1 gather + bias + ReLU + GEMM2 -> g_h2.
// Warp per node. Per 8 edges: 2 uniform int4 col loads, 8 uniform dinv
// gathers, 8 independent coalesced half2 row gathers.
__global__ void __launch_bounds__(256) k_fused1(const float* __restrict__ b1,
                                                const float* __restrict__ W2) {
    const int warp = threadIdx.x >> 5;
    const int l = threadIdx.x & 31;
    const int n = blockIdx.x * 8 + warp;
    if (n >= NNODES) return;

    const float din = g_dinv[n];
    const int deg = min(g_cursor[n], STRIDE);
    const int base = n * STRIDE;

    float2 sv = __half22float2(g_hh[(size_t)n * 32 + l]);
    const float sl = din * din;
    float a0 = sl * sv.x, a1 = sl * sv.y;     // self loop

    int s = 0;
    for (; s + 8 <= deg; s += 8) {
        int4 cA = *(const int4*)&g_colp[base + s];      // uniform 16B broadcast
        int4 cB = *(const int4*)&g_colp[base + s + 4];
        float d0 = g_dinv[cA.x], d1 = g_dinv[cA.y];
        float d2 = g_dinv[cA.z], d3 = g_dinv[cA.w];
        float d4 = g_dinv[cB.x], d5 = g_dinv[cB.y];
        float d6 = g_dinv[cB.z], d7 = g_dinv[cB.w];
        __half2 h0 = g_hh[(size_t)cA.x * 32 + l];
        __half2 h1 = g_hh[(size_t)cA.y * 32 + l];
        __half2 h2 = g_hh[(size_t)cA.z * 32 + l];
        __half2 h3 = g_hh[(size_t)cA.w * 32 + l];
        __half2 h4 = g_hh[(size_t)cB.x * 32 + l];
        __half2 h5 = g_hh[(size_t)cB.y * 32 + l];
        __half2 h6 = g_hh[(size_t)cB.z * 32 + l];
        __half2 h7 = g_hh[(size_t)cB.w * 32 + l];
        float w0 = din * d0, w1 = din * d1, w2 = din * d2, w3 = din * d3;
        float w4 = din * d4, w5 = din * d5, w6 = din * d6, w7 = din * d7;
        float2 f;
        f = __half22float2(h0); a0 = fmaf(w0, f.x, a0); a1 = fmaf(w0, f.y, a1);
        f = __half22float2(h1); a0 = fmaf(w1, f.x, a0); a1 = fmaf(w1, f.y, a1);
        f = __half22float2(h2); a0 = fmaf(w2, f.x, a0); a1 = fmaf(w2, f.y, a1);
        f = __half22float2(h3); a0 = fmaf(w3, f.x, a0); a1 = fmaf(w3, f.y, a1);
        f = __half22float2(h4); a0 = fmaf(w4, f.x, a0); a1 = fmaf(w4, f.y, a1);
        f = __half22float2(h5); a0 = fmaf(w5, f.x, a0); a1 = fmaf(w5, f.y, a1);
        f = __half22float2(h6); a0 = fmaf(w6, f.x, a0); a1 = fmaf(w6, f.y, a1);
        f = __half22float2(h7); a0 = fmaf(w7, f.x, a0); a1 = fmaf(w7, f.y, a1);
    }
    for (; s < deg; s++) {
        int c = g_colp[base + s];
        float w = din * g_dinv[c];
        float2 f = __half22float2(g_hh[(size_t)c * 32 + l]);
        a0 = fmaf(w, f.x, a0);
        a1 = fmaf(w, f.y, a1);
    }

    float v0 = fmaxf(a0 + b1[2 * l],     0.0f);
    float v1 = fmaxf(a1 + b1[2 * l + 1], 0.0f);

    // GEMM2: logits[n] = v @ W2 (64x2)
    float c0 = fmaf(v0, W2[(2 * l) * 2],     v1 * W2[(2 * l + 1) * 2]);
    float c1 = fmaf(v0, W2[(2 * l) * 2 + 1], v1 * W2[(2 * l + 1) * 2 + 1]);
    #pragma unroll
    for (int off = 16; off > 0; off >>= 1) {
        c0 += __shfl_down_sync(0xFFFFFFFFu, c0, off);
        c1 += __shfl_down_sync(0xFFFFFFFFu, c1, off);
    }
    if (l == 0) {
        g_h2[n * 2]     = c0;
        g_h2[n * 2 + 1] = c1;
    }
}

// K6: fused layer-2 gather + bias + softmax -> out.  Warp per node.
__global__ void k_fused2(const float* __restrict__ b2, float* __restrict__ out) {
    const int lane = threadIdx.x & 31;
    const int n = (blockIdx.x * blockDim.x + threadIdx.x) >> 5;
    if (n >= NNODES) return;
    const float din = g_dinv[n];
    const int deg = min(g_cursor[n], STRIDE);
    const int base = n * STRIDE;
    float a0 = 0.0f, a1 = 0.0f;
    for (int s = lane; s < deg; s += 32) {
        int c = g_colp[base + s];
        float w = din * g_dinv[c];
        a0 = fmaf(w, g_h2[c * 2],     a0);
        a1 = fmaf(w, g_h2[c * 2 + 1], a1);
    }
    #pragma unroll
    for (int off = 16; off > 0; off >>= 1) {
        a0 += __shfl_down_sync(0xFFFFFFFFu, a0, off);
        a1 += __shfl_down_sync(0xFFFFFFFFu, a1, off);
    }
    if (lane == 0) {
        float sl = din * din;
        float l0 = b2[0] + fmaf(sl, g_h2[n * 2],     a0);
        float l1 = b2[1] + fmaf(sl, g_h2[n * 2 + 1], a1);
        float m = fmaxf(l0, l1);
        float e0 = __expf(l0 - m), e1 = __expf(l1 - m);
        float inv = 1.0f / (e0 + e1);
        out[n * 2]     = e0 * inv;
        out[n * 2 + 1] = e1 * inv;
    }
}

extern "C" void kernel_launch(void* const* d_in, const int* in_sizes, int n_in,
                              void* d_out, int out_size) {
    const float* x  = (const float*)d_in[0];
    const int*   ei = (const int*)d_in[1];     // int32 (JAX x64 disabled)
    const float* W1 = (const float*)d_in[2];
    const float* b1 = (const float*)d_in[3];
    const float* W2 = (const float*)d_in[4];
    const float* b2 = (const float*)d_in[5];
    float* out = (float*)d_out;

    const int T = 256;
    k_zero   <<<(NNODES + T - 1) / T, T>>>();
    k_fill   <<<(NEDGES / 4 + T - 1) / T, T>>>(ei);
    k_dinv   <<<(NNODES + T - 1) / T, T>>>();
    k_gemm1  <<<(NNODES + 63) / 64, 256>>>(x, W1);
    k_fused1 <<<(NNODES + 7) / 8, 256>>>(b1, W2);
    k_fused2 <<<(NNODES * 32 + T - 1) / T, T>>>(b2, out);
}

// round 12
// speedup vs baseline: 1.8534x; 1.1650x over previous
#include <cuda_runtime.h>
#include <cuda_bf16.h>
#include <cuda_fp16.h>
#include <stdint.h>

#define NNODES 100000
#define NEDGES 1600000
#define FDIM   64
#define NCLS   2
#define STRIDE 64            // padded CSR row capacity (max deg ~45 for Poisson(16))

// Scratch (__device__ globals; no allocations allowed)
__device__ int   g_cursor[NNODES];
__device__ __align__(16) int g_colp[NNODES * STRIDE];  // padded CSR columns
__device__ float g_dinv[NNODES];
__device__ __align__(16) __half2 g_hh[NNODES * 32];    // x @ W1, fp16 pairs
__device__ float g_h2[NNODES * NCLS];                  // relu(agg1 + b1) @ W2

__device__ __forceinline__ int clampi(int v) {
    return min(max(v, 0), NNODES - 1);
}
__device__ __forceinline__ uint32_t s2u(const void* p) {
    return (uint32_t)__cvta_generic_to_shared(p);
}

// ---------------------------------------------------------------------------
// K1: zero cursor
__global__ void k_zero(void) {
    int i = blockIdx.x * blockDim.x + threadIdx.x;
    if (i < NNODES) g_cursor[i] = 0;
}

// K2: direct padded-CSR fill (cols only); 4 edges/thread via int4
__global__ void k_fill(const int* __restrict__ ei) {
    int i = blockIdx.x * blockDim.x + threadIdx.x;
    if (i >= NEDGES / 4) return;
    int4 rv = ((const int4*)ei)[i];
    int4 cv = ((const int4*)(ei + NEDGES))[i];
    #pragma unroll
    for (int j = 0; j < 4; j++) {
        int r = clampi(j == 0 ? rv.x : j == 1 ? rv.y : j == 2 ? rv.z : rv.w);
        int c = clampi(j == 0 ? cv.x : j == 1 ? cv.y : j == 2 ? cv.z : cv.w);
        int slot = atomicAdd(&g_cursor[r], 1);
        if (slot < STRIDE) g_colp[r * STRIDE + slot] = c;
    }
}

// K3: h = x @ W1 via HMMA m16n8k16 (fp16 in, fp32 acc, fp16 out).
// Block = 256 thr, tile 64 nodes x 64 cols. Also computes dinv for its nodes.
__global__ void __launch_bounds__(256) k_gemm1(const float* __restrict__ x,
                                               const float* __restrict__ W1) {
    __shared__ __half xsh[64][72];   // [node][k], 144B rows: ldmatrix conflict-free
    __shared__ __half wsh[64][72];   // [k][col]
    const int tid = threadIdx.x;
    const int base = blockIdx.x * 64;

    // dinv for this block's 64 nodes (cursor final after k_fill)
    if (tid < 64 && base + tid < NNODES)
        g_dinv[base + tid] = rsqrtf((float)g_cursor[base + tid] + 1.0f);

    // Convert W1 and x tile to fp16 smem
    for (int i = tid; i < 64 * 16; i += 256) {          // W1: 1024 float4
        const int k = i >> 4, seg = i & 15;
        float4 v = ((const float4*)W1)[i];
        *(__half2*)&wsh[k][seg * 4]     = __floats2half2_rn(v.x, v.y);
        *(__half2*)&wsh[k][seg * 4 + 2] = __floats2half2_rn(v.z, v.w);
    }
    for (int i = tid; i < 64 * 16; i += 256) {          // x tile
        const int r = i >> 4, seg = i & 15;
        const int node = base + r;
        float4 v = (node < NNODES) ? ((const float4*)(x + (size_t)node * FDIM))[seg]
                                   : make_float4(0.f, 0.f, 0.f, 0.f);
        *(__half2*)&xsh[r][seg * 4]     = __floats2half2_rn(v.x, v.y);
        *(__half2*)&xsh[r][seg * 4 + 2] = __floats2half2_rn(v.z, v.w);
    }
    __syncthreads();

    const int warp = tid >> 5, lane = tid & 31;
    const int mi = warp & 3;               // M tile: rows 16*mi..16*mi+15
    const int nbase = (warp >> 2) * 32;    // N offset: 0 or 32

    float d[4][4];
    #pragma unroll
    for (int j = 0; j < 4; j++)
        #pragma unroll
        for (int i = 0; i < 4; i++) d[j][i] = 0.0f;

    #pragma unroll
    for (int kt = 0; kt < 4; kt++) {
        uint32_t a0, a1, a2, a3;
        {   // A frag m16k16: lanes 0-15 rows @k0, 16-31 rows @k8
            uint32_t addr = s2u(&xsh[mi * 16 + (lane & 15)][kt * 16 + (lane >> 4) * 8]);
            asm volatile("ldmatrix.sync.aligned.m8n8.x4.shared.b16 {%0,%1,%2,%3},[%4];"
                         : "=r"(a0), "=r"(a1), "=r"(a2), "=r"(a3) : "r"(addr));
        }
        #pragma unroll
        for (int h = 0; h < 2; h++) {   // two n16 halves -> 4 n8 subtiles
            uint32_t b0, b1, b2, b3;
            uint32_t addr = s2u(&wsh[kt * 16 + (lane & 15)]
                                    [nbase + h * 16 + (lane >> 4) * 8]);
            asm volatile("ldmatrix.sync.aligned.m8n8.x4.trans.shared.b16 {%0,%1,%2,%3},[%4];"
                         : "=r"(b0), "=r"(b1), "=r"(b2), "=r"(b3) : "r"(addr));
            asm volatile("mma.sync.aligned.m16n8k16.row.col.f32.f16.f16.f32 "
                         "{%0,%1,%2,%3},{%4,%5,%6,%7},{%8,%9},{%0,%1,%2,%3};"
                         : "+f"(d[h * 2][0]), "+f"(d[h * 2][1]),
                           "+f"(d[h * 2][2]), "+f"(d[h * 2][3])
                         : "r"(a0), "r"(a1), "r"(a2), "r"(a3), "r"(b0), "r"(b1));
            asm volatile("mma.sync.aligned.m16n8k16.row.col.f32.f16.f16.f32 "
                         "{%0,%1,%2,%3},{%4,%5,%6,%7},{%8,%9},{%0,%1,%2,%3};"
                         : "+f"(d[h * 2 + 1][0]), "+f"(d[h * 2 + 1][1]),
                           "+f"(d[h * 2 + 1][2]), "+f"(d[h * 2 + 1][3])
                         : "r"(a0), "r"(a1), "r"(a2), "r"(a3), "r"(b2), "r"(b3));
        }
    }

    // Store: d[j] covers n8 at nbase+j*8. d0,d1 -> row lane/4, cols (lane%4)*2,+1.
    const int row0 = base + mi * 16 + (lane >> 2);
    #pragma unroll
    for (int j = 0; j < 4; j++) {
        const int hp = (nbase + j * 8) / 2 + (lane & 3);   // half2 index in row
        if (row0 < NNODES)
            g_hh[(size_t)row0 * 32 + hp] = __floats2half2_rn(d[j][0], d[j][1]);
        if (row0 + 8 < NNODES)
            g_hh[(size_t)(row0 + 8) * 32 + hp] = __floats2half2_rn(d[j][2], d[j][3]);
    }
}

// K4: fused layer-1 gather + bias + ReLU + GEMM2 -> g_h2.
// Warp per node. Per 8 edges: 2 uniform int4 col loads, 8 uniform dinv
// gathers, 8 independent coalesced half2 row gathers.
__global__ void __launch_bounds__(256) k_fused1(const float* __restrict__ b1,
                                                const float* __restrict__ W2) {
    const int warp = threadIdx.x >> 5;
    const int l = threadIdx.x & 31;
    const int n = blockIdx.x * 8 + warp;
    if (n >= NNODES) return;

    const float din = g_dinv[n];
    const int deg = min(g_cursor[n], STRIDE);
    const int base = n * STRIDE;

    float2 sv = __half22float2(g_hh[(size_t)n * 32 + l]);
    const float sl = din * din;
    float a0 = sl * sv.x, a1 = sl * sv.y;     // self loop

    int s = 0;
    for (; s + 8 <= deg; s += 8) {
        int4 cA = *(const int4*)&g_colp[base + s];      // uniform 16B broadcast
        int4 cB = *(const int4*)&g_colp[base + s + 4];
        float d0 = g_dinv[cA.x], d1 = g_dinv[cA.y];
        float d2 = g_dinv[cA.z], d3 = g_dinv[cA.w];
        float d4 = g_dinv[cB.x], d5 = g_dinv[cB.y];
        float d6 = g_dinv[cB.z], d7 = g_dinv[cB.w];
        __half2 h0 = g_hh[(size_t)cA.x * 32 + l];
        __half2 h1 = g_hh[(size_t)cA.y * 32 + l];
        __half2 h2 = g_hh[(size_t)cA.z * 32 + l];
        __half2 h3 = g_hh[(size_t)cA.w * 32 + l];
        __half2 h4 = g_hh[(size_t)cB.x * 32 + l];
        __half2 h5 = g_hh[(size_t)cB.y * 32 + l];
        __half2 h6 = g_hh[(size_t)cB.z * 32 + l];
        __half2 h7 = g_hh[(size_t)cB.w * 32 + l];
        float w0 = din * d0, w1 = din * d1, w2 = din * d2, w3 = din * d3;
        float w4 = din * d4, w5 = din * d5, w6 = din * d6, w7 = din * d7;
        float2 f;
        f = __half22float2(h0); a0 = fmaf(w0, f.x, a0); a1 = fmaf(w0, f.y, a1);
        f = __half22float2(h1); a0 = fmaf(w1, f.x, a0); a1 = fmaf(w1, f.y, a1);
        f = __half22float2(h2); a0 = fmaf(w2, f.x, a0); a1 = fmaf(w2, f.y, a1);
        f = __half22float2(h3); a0 = fmaf(w3, f.x, a0); a1 = fmaf(w3, f.y, a1);
        f = __half22float2(h4); a0 = fmaf(w4, f.x, a0); a1 = fmaf(w4, f.y, a1);
        f = __half22float2(h5); a0 = fmaf(w5, f.x, a0); a1 = fmaf(w5, f.y, a1);
        f = __half22float2(h6); a0 = fmaf(w6, f.x, a0); a1 = fmaf(w6, f.y, a1);
        f = __half22float2(h7); a0 = fmaf(w7, f.x, a0); a1 = fmaf(w7, f.y, a1);
    }
    for (; s < deg; s++) {
        int c = g_colp[base + s];
        float w = din * g_dinv[c];
        float2 f = __half22float2(g_hh[(size_t)c * 32 + l]);
        a0 = fmaf(w, f.x, a0);
        a1 = fmaf(w, f.y, a1);
    }

    float v0 = fmaxf(a0 + b1[2 * l],     0.0f);
    float v1 = fmaxf(a1 + b1[2 * l + 1], 0.0f);

    // GEMM2: logits[n] = v @ W2 (64x2)
    float c0 = fmaf(v0, W2[(2 * l) * 2],     v1 * W2[(2 * l + 1) * 2]);
    float c1 = fmaf(v0, W2[(2 * l) * 2 + 1], v1 * W2[(2 * l + 1) * 2 + 1]);
    #pragma unroll
    for (int off = 16; off > 0; off >>= 1) {
        c0 += __shfl_down_sync(0xFFFFFFFFu, c0, off);
        c1 += __shfl_down_sync(0xFFFFFFFFu, c1, off);
    }
    if (l == 0) {
        g_h2[n * 2]     = c0;
        g_h2[n * 2 + 1] = c1;
    }
}

// K5: fused layer-2 gather + bias + softmax -> out.  Warp per node.
__global__ void k_fused2(const float* __restrict__ b2, float* __restrict__ out) {
    const int lane = threadIdx.x & 31;
    const int n = (blockIdx.x * blockDim.x + threadIdx.x) >> 5;
    if (n >= NNODES) return;
    const float din = g_dinv[n];
    const int deg = min(g_cursor[n], STRIDE);
    const int base = n * STRIDE;
    float a0 = 0.0f, a1 = 0.0f;
    for (int s = lane; s < deg; s += 32) {
        int c = g_colp[base + s];
        float w = din * g_dinv[c];
        a0 = fmaf(w, g_h2[c * 2],     a0);
        a1 = fmaf(w, g_h2[c * 2 + 1], a1);
    }
    #pragma unroll
    for (int off = 16; off > 0; off >>= 1) {
        a0 += __shfl_down_sync(0xFFFFFFFFu, a0, off);
        a1 += __shfl_down_sync(0xFFFFFFFFu, a1, off);
    }
    if (lane == 0) {
        float sl = din * din;
        float l0 = b2[0] + fmaf(sl, g_h2[n * 2],     a0);
        float l1 = b2[1] + fmaf(sl, g_h2[n * 2 + 1], a1);
        float m = fmaxf(l0, l1);
        float e0 = __expf(l0 - m), e1 = __expf(l1 - m);
        float inv = 1.0f / (e0 + e1);
        out[n * 2]     = e0 * inv;
        out[n * 2 + 1] = e1 * inv;
    }
}

extern "C" void kernel_launch(void* const* d_in, const int* in_sizes, int n_in,
                              void* d_out, int out_size) {
    const float* x  = (const float*)d_in[0];
    const int*   ei = (const int*)d_in[1];     // int32 (JAX x64 disabled)
    const float* W1 = (const float*)d_in[2];
    const float* b1 = (const float*)d_in[3];
    const float* W2 = (const float*)d_in[4];
    const float* b2 = (const float*)d_in[5];
    float* out = (float*)d_out;

    const int T = 256;
    k_zero   <<<(NNODES + T - 1) / T, T>>>();
    k_fill   <<<(NEDGES / 4 + T - 1) / T, T>>>(ei);
    k_gemm1  <<<(NNODES + 63) / 64, 256>>>(x, W1);
    k_fused1 <<<(NNODES + 7) / 8, 256>>>(b1, W2);
    k_fused2 <<<(NNODES * 32 + T - 1) / T, T>>>(b2, out);
}